// round 1
// baseline (speedup 1.0000x reference)
#include <cuda_runtime.h>
#include <math.h>
#include <stdint.h>

// Problem constants (fixed shapes: B=4, S=4096, D=1024)
static constexpr int S_LEN = 4096;
static constexpr int D_DIM = 1024;
static constexpr int B_DIM = 4;
static constexpr int FD    = 4 * D_DIM;   // 4096 (context width)
static constexpr int HD    = 2 * D_DIM;   // 2048 (hidden width)
static constexpr int NROWS = B_DIM * S_LEN; // 16384

// Scratch (device globals: no allocation allowed in kernel_launch)
__device__ float g_omega[(size_t)NROWS * D_DIM];  //  64 MB
__device__ float g_ctx  [(size_t)NROWS * FD];     // 256 MB
__device__ float g_h1   [(size_t)NROWS * HD];     // 128 MB

// ---------------------------------------------------------------------------
// SGEMM: C[M,N] = A[M,K] * B[N,K]^T + bias[N]   (both operands K-major)
// Optional epilogues: exact GELU, residual add.
// 128x128 block tile, BK=8, 256 threads, 8x8 per-thread microtile.
// ---------------------------------------------------------------------------
template<bool GELU, bool RES>
__global__ __launch_bounds__(256, 2)
void sgemm_kernel(const float* __restrict__ A, const float* __restrict__ B,
                  const float* __restrict__ bias, const float* __restrict__ res,
                  float* __restrict__ C, int M, int N, int K)
{
    constexpr int BM = 128, BN = 128, BK = 8;
    __shared__ float As[BK][BM + 4];
    __shared__ float Bs[BK][BN + 4];

    const int tid = threadIdx.x;
    const int tx  = tid & 15;    // 16 column groups
    const int ty  = tid >> 4;    // 16 row groups
    const int m0  = blockIdx.y * BM;
    const int n0  = blockIdx.x * BN;

    const float* Ab = A + (size_t)m0 * K;
    const float* Bb = B + (size_t)n0 * K;

    const int lrow = tid >> 1;        // 0..127
    const int lcol = (tid & 1) * 4;   // 0 or 4

    float acc[8][8];
    #pragma unroll
    for (int i = 0; i < 8; i++)
        #pragma unroll
        for (int j = 0; j < 8; j++) acc[i][j] = 0.0f;

    for (int k0 = 0; k0 < K; k0 += BK) {
        float4 av = *(const float4*)(Ab + (size_t)lrow * K + k0 + lcol);
        float4 bv = *(const float4*)(Bb + (size_t)lrow * K + k0 + lcol);
        __syncthreads();
        As[lcol + 0][lrow] = av.x; As[lcol + 1][lrow] = av.y;
        As[lcol + 2][lrow] = av.z; As[lcol + 3][lrow] = av.w;
        Bs[lcol + 0][lrow] = bv.x; Bs[lcol + 1][lrow] = bv.y;
        Bs[lcol + 2][lrow] = bv.z; Bs[lcol + 3][lrow] = bv.w;
        __syncthreads();
        #pragma unroll
        for (int kk = 0; kk < BK; kk++) {
            float a[8], b[8];
            *(float4*)(a)     = *(const float4*)&As[kk][ty * 8];
            *(float4*)(a + 4) = *(const float4*)&As[kk][ty * 8 + 4];
            *(float4*)(b)     = *(const float4*)&Bs[kk][tx * 8];
            *(float4*)(b + 4) = *(const float4*)&Bs[kk][tx * 8 + 4];
            #pragma unroll
            for (int i = 0; i < 8; i++)
                #pragma unroll
                for (int j = 0; j < 8; j++)
                    acc[i][j] = fmaf(a[i], b[j], acc[i][j]);
        }
    }

    #pragma unroll
    for (int i = 0; i < 8; i++) {
        const int row = m0 + ty * 8 + i;
        #pragma unroll
        for (int j = 0; j < 8; j++) {
            const int col = n0 + tx * 8 + j;
            float v = acc[i][j] + bias[col];
            if (GELU) v = 0.5f * v * (1.0f + erff(v * 0.70710678118654752f));
            if (RES)  v += res[(size_t)row * N + col];
            C[(size_t)row * N + col] = v;
        }
    }
}

// ---------------------------------------------------------------------------
// Fused scan kernel: per (b, d) channel, sequentially over S:
//   w      = omega * exp(log_scale[d]) / sqrt(s+1)
//   phi    = cumsum_s(w)
//   cm_r/i = x * cos(phi) / x * sin(phi)
//   mem_r/i= cumsum_s(cm_r/i) / (s+1)
//   ret_r  = mem_r*cos + mem_i*sin ; ret_i = mem_i*cos - mem_r*sin
// writes context[b,s, {0,1,2,3}*D + d].
// Block = 32(s) x 32(d); grid = (D/32, B). Tiles role-swap through smem so
// loads/stores are coalesced along d while the scan runs on warp lanes along s.
// ---------------------------------------------------------------------------
__global__ __launch_bounds__(1024)
void scan_kernel(const float* __restrict__ x, const float* __restrict__ omega,
                 const float* __restrict__ log_scale, float* __restrict__ ctx)
{
    __shared__ float xs[32][33];
    __shared__ float os[32][33];
    __shared__ float ob[4][32][33];

    const int b  = blockIdx.y;
    const int d0 = blockIdx.x * 32;
    const int tx = threadIdx.x;   // load phase: d-local ; scan phase: s-local (lane)
    const int ty = threadIdx.y;   // load phase: s-local ; scan phase: d-local (warp)

    const float escale = expf(log_scale[d0 + ty]);  // per-warp uniform in scan phase

    const float* xp = x     + (size_t)b * S_LEN * D_DIM;
    const float* op = omega + (size_t)b * S_LEN * D_DIM;
    float*       cp = ctx   + (size_t)b * S_LEN * FD;

    float c0 = 0.0f, c1 = 0.0f, c2 = 0.0f;  // carries: phi, cm_real, cm_imag

    for (int s0 = 0; s0 < S_LEN; s0 += 32) {
        // coalesced load: thread(tx=d, ty=s)
        xs[ty][tx] = xp[(size_t)(s0 + ty) * D_DIM + d0 + tx];
        os[ty][tx] = op[(size_t)(s0 + ty) * D_DIM + d0 + tx];
        __syncthreads();

        // scan phase: lane=tx is s-local, warp=ty is d-local
        const float pos = (float)(s0 + tx + 1);
        float w = os[tx][ty] * escale * rsqrtf(pos);

        float pl = w;
        #pragma unroll
        for (int off = 1; off < 32; off <<= 1) {
            float t = __shfl_up_sync(0xffffffffu, pl, off);
            if (tx >= off) pl += t;
        }
        const float phi = c0 + pl;
        c0 += __shfl_sync(0xffffffffu, pl, 31);

        float sv, cv;
        sincosf(phi, &sv, &cv);
        const float xv  = xs[tx][ty];
        const float cmr = xv * cv;
        const float cmi = xv * sv;

        float pr = cmr;
        #pragma unroll
        for (int off = 1; off < 32; off <<= 1) {
            float t = __shfl_up_sync(0xffffffffu, pr, off);
            if (tx >= off) pr += t;
        }
        float pi = cmi;
        #pragma unroll
        for (int off = 1; off < 32; off <<= 1) {
            float t = __shfl_up_sync(0xffffffffu, pi, off);
            if (tx >= off) pi += t;
        }

        const float memr = (c1 + pr) / pos;
        const float memi = (c2 + pi) / pos;
        c1 += __shfl_sync(0xffffffffu, pr, 31);
        c2 += __shfl_sync(0xffffffffu, pi, 31);

        const float retr = memr * cv + memi * sv;
        const float reti = memi * cv - memr * sv;

        ob[0][tx][ty] = cmr;
        ob[1][tx][ty] = cmi;
        ob[2][tx][ty] = retr;
        ob[3][tx][ty] = reti;
        __syncthreads();

        // coalesced store: thread(tx=d, ty=s)
        const size_t ro = (size_t)(s0 + ty) * FD + d0 + tx;
        cp[ro]             = ob[0][ty][tx];
        cp[ro + D_DIM]     = ob[1][ty][tx];
        cp[ro + 2 * D_DIM] = ob[2][ty][tx];
        cp[ro + 3 * D_DIM] = ob[3][ty][tx];
    }
}

// ---------------------------------------------------------------------------
// In-place LayerNorm over last dim (FD=4096). One 256-thread block per row.
// Row cached in shared memory (16 KB) so gmem is touched once each way.
// ---------------------------------------------------------------------------
__global__ __launch_bounds__(256)
void ln_kernel(float* __restrict__ ctx, const float* __restrict__ gamma,
               const float* __restrict__ beta)
{
    __shared__ float buf[FD];
    __shared__ float red1[8], red2[8];

    float* row = ctx + (size_t)blockIdx.x * FD;
    const int tid = threadIdx.x;

    float s1 = 0.0f, s2 = 0.0f;
    #pragma unroll
    for (int i = 0; i < 4; i++) {
        const int idx = (tid + i * 256) * 4;
        float4 v = *(const float4*)(row + idx);
        *(float4*)(buf + idx) = v;
        s1 += v.x + v.y + v.z + v.w;
        s2 += v.x * v.x + v.y * v.y + v.z * v.z + v.w * v.w;
    }
    #pragma unroll
    for (int off = 16; off > 0; off >>= 1) {
        s1 += __shfl_down_sync(0xffffffffu, s1, off);
        s2 += __shfl_down_sync(0xffffffffu, s2, off);
    }
    if ((tid & 31) == 0) { red1[tid >> 5] = s1; red2[tid >> 5] = s2; }
    __syncthreads();
    if (tid < 32) {
        s1 = (tid < 8) ? red1[tid] : 0.0f;
        s2 = (tid < 8) ? red2[tid] : 0.0f;
        #pragma unroll
        for (int off = 4; off > 0; off >>= 1) {
            s1 += __shfl_down_sync(0xffffffffu, s1, off);
            s2 += __shfl_down_sync(0xffffffffu, s2, off);
        }
        if (tid == 0) { red1[0] = s1; red2[0] = s2; }
    }
    __syncthreads();

    const float mean = red1[0] * (1.0f / FD);
    const float var  = red2[0] * (1.0f / FD) - mean * mean;
    const float inv  = rsqrtf(var + 1e-5f);

    #pragma unroll
    for (int i = 0; i < 4; i++) {
        const int idx = (tid + i * 256) * 4;
        float4 v  = *(const float4*)(buf + idx);
        float4 g  = *(const float4*)(gamma + idx);
        float4 be = *(const float4*)(beta + idx);
        v.x = (v.x - mean) * inv * g.x + be.x;
        v.y = (v.y - mean) * inv * g.y + be.y;
        v.z = (v.z - mean) * inv * g.z + be.z;
        v.w = (v.w - mean) * inv * g.w + be.w;
        *(float4*)(row + idx) = v;
    }
}

// ---------------------------------------------------------------------------
extern "C" void kernel_launch(void* const* d_in, const int* in_sizes, int n_in,
                              void* d_out, int out_size)
{
    const float* x         = (const float*)d_in[0];
    const float* W_omega   = (const float*)d_in[1];
    const float* b_omega   = (const float*)d_in[2];
    const float* log_scale = (const float*)d_in[3];
    const float* ln_gamma  = (const float*)d_in[4];
    const float* ln_beta   = (const float*)d_in[5];
    const float* W1        = (const float*)d_in[6];
    const float* b1        = (const float*)d_in[7];
    const float* W2        = (const float*)d_in[8];
    const float* b2        = (const float*)d_in[9];
    float* out = (float*)d_out;

    float *omega_p, *ctx_p, *h1_p;
    cudaGetSymbolAddress((void**)&omega_p, g_omega);
    cudaGetSymbolAddress((void**)&ctx_p,   g_ctx);
    cudaGetSymbolAddress((void**)&h1_p,    g_h1);

    // 1) omega = x @ W_omega^T + b_omega
    sgemm_kernel<false, false><<<dim3(D_DIM / 128, NROWS / 128), 256>>>(
        x, W_omega, b_omega, nullptr, omega_p, NROWS, D_DIM, D_DIM);

    // 2) fused scans -> context [B,S,4D]
    scan_kernel<<<dim3(D_DIM / 32, B_DIM), dim3(32, 32)>>>(
        x, omega_p, log_scale, ctx_p);

    // 3) in-place LayerNorm over 4D
    ln_kernel<<<NROWS, 256>>>(ctx_p, ln_gamma, ln_beta);

    // 4) h1 = GELU(ctx @ W1^T + b1)
    sgemm_kernel<true, false><<<dim3(HD / 128, NROWS / 128), 256>>>(
        ctx_p, W1, b1, nullptr, h1_p, NROWS, HD, FD);

    // 5) out = x + h1 @ W2^T + b2
    sgemm_kernel<false, true><<<dim3(D_DIM / 128, NROWS / 128), 256>>>(
        h1_p, W2, b2, x, out, NROWS, D_DIM, HD);
}

// round 3
// speedup vs baseline: 2.6294x; 2.6294x over previous
#include <cuda_runtime.h>
#include <cuda_bf16.h>
#include <math.h>
#include <stdint.h>

// Shapes fixed: B=4, S=4096, D=1024
static constexpr int S_LEN = 4096;
static constexpr int D_DIM = 1024;
static constexpr int B_DIM = 4;
static constexpr int FD    = 4 * D_DIM;     // 4096
static constexpr int HD    = 2 * D_DIM;     // 2048
static constexpr int NROWS = B_DIM * S_LEN; // 16384

// ---------------- scratch (device globals; no allocs allowed) ----------------
__device__ float g_omega[(size_t)NROWS * D_DIM];   // 64 MB
__device__ float g_ctx  [(size_t)NROWS * FD];      // 256 MB
__device__ __nv_bfloat16 g_xh [(size_t)NROWS * D_DIM];
__device__ __nv_bfloat16 g_xl [(size_t)NROWS * D_DIM];
__device__ __nv_bfloat16 g_w0h[(size_t)D_DIM * D_DIM];
__device__ __nv_bfloat16 g_w0l[(size_t)D_DIM * D_DIM];
__device__ __nv_bfloat16 g_w1h[(size_t)HD * FD];
__device__ __nv_bfloat16 g_w1l[(size_t)HD * FD];
__device__ __nv_bfloat16 g_w2h[(size_t)D_DIM * HD];
__device__ __nv_bfloat16 g_w2l[(size_t)D_DIM * HD];
__device__ __nv_bfloat16 g_ch [(size_t)NROWS * FD];
__device__ __nv_bfloat16 g_cl [(size_t)NROWS * FD];
__device__ __nv_bfloat16 g_h1h[(size_t)NROWS * HD];
__device__ __nv_bfloat16 g_h1l[(size_t)NROWS * HD];

// ---------------- PTX helpers (stable ISA only: cp.async / ldmatrix / mma) ---
__device__ __forceinline__ uint32_t smem_u32(const void* p) {
    uint32_t a;
    asm("{ .reg .u64 t; cvta.to.shared.u64 t, %1; cvt.u32.u64 %0, t; }" : "=r"(a) : "l"(p));
    return a;
}

__device__ __forceinline__ void cp_async16(uint32_t saddr, const void* gptr) {
    asm volatile("cp.async.cg.shared.global [%0], [%1], 16;" :: "r"(saddr), "l"(gptr));
}
__device__ __forceinline__ void cp_commit() { asm volatile("cp.async.commit_group;" ::: "memory"); }
template <int N> __device__ __forceinline__ void cp_wait() {
    asm volatile("cp.async.wait_group %0;" :: "n"(N) : "memory");
}

#define LDMX4(r0, r1, r2, r3, addr)                                              \
    asm volatile("ldmatrix.sync.aligned.m8n8.x4.shared.b16 {%0,%1,%2,%3}, [%4];" \
        : "=r"(r0), "=r"(r1), "=r"(r2), "=r"(r3) : "r"(addr))

#define MMA16816(d, a, b0, b1)                                                   \
    asm volatile("mma.sync.aligned.m16n8k16.row.col.f32.bf16.bf16.f32 "          \
        "{%0,%1,%2,%3}, {%4,%5,%6,%7}, {%8,%9}, {%0,%1,%2,%3};"                  \
        : "+f"((d)[0]), "+f"((d)[1]), "+f"((d)[2]), "+f"((d)[3])                 \
        : "r"((a)[0]), "r"((a)[1]), "r"((a)[2]), "r"((a)[3]), "r"(b0), "r"(b1))

// ---------------------------------------------------------------------------
// Split-bf16 tensor-core GEMM: C[M,N] = A[M,K] * B[N,K]^T  (3-term hi/lo)
// 128x128 tile, BK=64 bf16 (128B rows, XOR row&7 swizzle), 3-stage cp.async,
// 8 warps (2x4), warp tile 64x32, mma.sync.m16n8k16 bf16 -> fp32.
// EPI: 0 = bias fp32 out; 1 = bias+GELU split bf16 out; 2 = bias+res fp32 out
// ---------------------------------------------------------------------------
static constexpr int TILE_B   = 128 * 128;        // 16 KB, one 128x64 bf16 tile
static constexpr int STAGE_B  = 4 * TILE_B;       // Ah, Al, Bh, Bl = 64 KB
static constexpr int NSTAGE   = 3;
static constexpr int GEMM_DSM = NSTAGE * STAGE_B; // 192 KB

template <int EPI>
__global__ __launch_bounds__(256, 1)
void gemm_tc_kernel(const __nv_bfloat16* __restrict__ Ah, const __nv_bfloat16* __restrict__ Al,
                    const __nv_bfloat16* __restrict__ Bh, const __nv_bfloat16* __restrict__ Bl,
                    const float* __restrict__ bias, const float* __restrict__ res,
                    float* __restrict__ outf, __nv_bfloat16* __restrict__ outh,
                    __nv_bfloat16* __restrict__ outl, int M, int N, int K)
{
    extern __shared__ __align__(1024) unsigned char dsm[];

    const int tid = threadIdx.x;
    const int wid = tid >> 5;
    const int lid = tid & 31;
    const int m0 = blockIdx.y * 128;
    const int n0 = blockIdx.x * 128;
    const uint32_t dsm_b = smem_u32(dsm);

    const int warpM = wid >> 2;          // 0..1  (64-row strip)
    const int warpN = wid & 3;           // 0..3  (32-col strip)
    const int rl = lid & 15;             // ldmatrix row-in-16
    const int ch = lid >> 4;             // ldmatrix chunk select (k8 half)

    const __nv_bfloat16* tiles[4] = {
        Ah + (size_t)m0 * K, Al + (size_t)m0 * K,
        Bh + (size_t)n0 * K, Bl + (size_t)n0 * K };

    const int nchunk = K >> 6;           // BK = 64

    auto load_chunk = [&](int chunk) {
        const uint32_t sb = dsm_b + (chunk % NSTAGE) * STAGE_B;
        const int koff = chunk << 6;
        #pragma unroll
        for (int t = 0; t < 4; t++) {
            #pragma unroll
            for (int i = 0; i < 4; i++) {
                const int u   = i * 256 + tid;   // 0..1023: 16B units in tile
                const int row = u >> 3;
                const int c   = u & 7;
                const void* gp = tiles[t] + (size_t)row * K + koff + c * 8;
                const uint32_t sa = sb + t * TILE_B + row * 128 +
                                    ((c ^ (row & 7)) << 4);
                cp_async16(sa, gp);
            }
        }
        cp_commit();
    };

    float acc[4][4][4];
    #pragma unroll
    for (int mi = 0; mi < 4; mi++)
        #pragma unroll
        for (int ni = 0; ni < 4; ni++)
            #pragma unroll
            for (int r = 0; r < 4; r++) acc[mi][ni][r] = 0.0f;

    load_chunk(0);
    load_chunk(1);

    for (int c = 0; c < nchunk; c++) {
        if (c < nchunk - 1) cp_wait<1>(); else cp_wait<0>();
        __syncthreads();
        if (c + 2 < nchunk) load_chunk(c + 2);

        const uint32_t st = dsm_b + (c % NSTAGE) * STAGE_B;

        #pragma unroll
        for (int ks = 0; ks < 4; ks++) {
            const int kchunk = (ks << 1) | ch;   // logical 16B chunk (k8 index)
            uint32_t ah[4][4], al[4][4], bh[2][4], bl[2][4];

            #pragma unroll
            for (int mi = 0; mi < 4; mi++) {
                const int row = warpM * 64 + mi * 16 + rl;
                const uint32_t ad = st + row * 128 + ((kchunk ^ (row & 7)) << 4);
                LDMX4(ah[mi][0], ah[mi][1], ah[mi][2], ah[mi][3], ad);
                LDMX4(al[mi][0], al[mi][1], al[mi][2], al[mi][3], ad + TILE_B);
            }
            #pragma unroll
            for (int nj = 0; nj < 2; nj++) {
                const int row = warpN * 32 + nj * 16 + rl;
                const uint32_t bd = st + 2 * TILE_B + row * 128 +
                                    ((kchunk ^ (row & 7)) << 4);
                LDMX4(bh[nj][0], bh[nj][1], bh[nj][2], bh[nj][3], bd);
                LDMX4(bl[nj][0], bl[nj][1], bl[nj][2], bl[nj][3], bd + TILE_B);
            }

            #pragma unroll
            for (int mi = 0; mi < 4; mi++)
                #pragma unroll
                for (int ni = 0; ni < 4; ni++) {
                    const int nj = ni >> 1, sel = ni & 1;
                    MMA16816(acc[mi][ni], ah[mi], bh[nj][sel], bh[nj][2 + sel]);
                    MMA16816(acc[mi][ni], ah[mi], bl[nj][sel], bl[nj][2 + sel]);
                    MMA16816(acc[mi][ni], al[mi], bh[nj][sel], bh[nj][2 + sel]);
                }
        }
    }

    // ---------------- epilogue (direct from registers) ----------------
    const int g = lid >> 2, q = lid & 3;
    #pragma unroll
    for (int mi = 0; mi < 4; mi++) {
        #pragma unroll
        for (int ni = 0; ni < 4; ni++) {
            const int row = m0 + warpM * 64 + mi * 16 + g;
            const int col = n0 + warpN * 32 + ni * 8 + q * 2;
            const float2 bb = *(const float2*)(bias + col);
            float v[4];
            v[0] = acc[mi][ni][0] + bb.x;
            v[1] = acc[mi][ni][1] + bb.y;
            v[2] = acc[mi][ni][2] + bb.x;
            v[3] = acc[mi][ni][3] + bb.y;
            const size_t o0 = (size_t)row * N + col;
            const size_t o1 = (size_t)(row + 8) * N + col;
            if (EPI == 1) {
                #pragma unroll
                for (int r = 0; r < 4; r++)
                    v[r] = 0.5f * v[r] * (1.0f + erff(v[r] * 0.70710678118654752f));
                __nv_bfloat16 h0 = __float2bfloat16(v[0]);
                __nv_bfloat16 h1 = __float2bfloat16(v[1]);
                __nv_bfloat16 h2 = __float2bfloat16(v[2]);
                __nv_bfloat16 h3 = __float2bfloat16(v[3]);
                *(__nv_bfloat162*)(outh + o0) = __nv_bfloat162(h0, h1);
                *(__nv_bfloat162*)(outh + o1) = __nv_bfloat162(h2, h3);
                *(__nv_bfloat162*)(outl + o0) = __nv_bfloat162(
                    __float2bfloat16(v[0] - __bfloat162float(h0)),
                    __float2bfloat16(v[1] - __bfloat162float(h1)));
                *(__nv_bfloat162*)(outl + o1) = __nv_bfloat162(
                    __float2bfloat16(v[2] - __bfloat162float(h2)),
                    __float2bfloat16(v[3] - __bfloat162float(h3)));
            } else if (EPI == 2) {
                const float2 r0 = *(const float2*)(res + o0);
                const float2 r1 = *(const float2*)(res + o1);
                *(float2*)(outf + o0) = make_float2(v[0] + r0.x, v[1] + r0.y);
                *(float2*)(outf + o1) = make_float2(v[2] + r1.x, v[3] + r1.y);
            } else {
                *(float2*)(outf + o0) = make_float2(v[0], v[1]);
                *(float2*)(outf + o1) = make_float2(v[2], v[3]);
            }
        }
    }
}

// ---------------------------------------------------------------------------
// fp32 -> bf16 hi/lo split
// ---------------------------------------------------------------------------
__global__ __launch_bounds__(256)
void split_kernel(const float* __restrict__ in, __nv_bfloat16* __restrict__ hi,
                  __nv_bfloat16* __restrict__ lo, int n4)
{
    int i = blockIdx.x * blockDim.x + threadIdx.x;
    if (i >= n4) return;
    float4 v = ((const float4*)in)[i];
    __nv_bfloat16 h0 = __float2bfloat16(v.x), h1 = __float2bfloat16(v.y);
    __nv_bfloat16 h2 = __float2bfloat16(v.z), h3 = __float2bfloat16(v.w);
    __nv_bfloat162* hp = (__nv_bfloat162*)hi;
    __nv_bfloat162* lp = (__nv_bfloat162*)lo;
    hp[2 * i]     = __nv_bfloat162(h0, h1);
    hp[2 * i + 1] = __nv_bfloat162(h2, h3);
    lp[2 * i]     = __nv_bfloat162(__float2bfloat16(v.x - __bfloat162float(h0)),
                                   __float2bfloat16(v.y - __bfloat162float(h1)));
    lp[2 * i + 1] = __nv_bfloat162(__float2bfloat16(v.z - __bfloat162float(h2)),
                                   __float2bfloat16(v.w - __bfloat162float(h3)));
}

// ---------------------------------------------------------------------------
// Fused sequential scans (validated in R1)
// ---------------------------------------------------------------------------
__global__ __launch_bounds__(1024)
void scan_kernel(const float* __restrict__ x, const float* __restrict__ omega,
                 const float* __restrict__ log_scale, float* __restrict__ ctx)
{
    __shared__ float xs[32][33];
    __shared__ float os[32][33];
    __shared__ float ob[4][32][33];

    const int b  = blockIdx.y;
    const int d0 = blockIdx.x * 32;
    const int tx = threadIdx.x;
    const int ty = threadIdx.y;

    const float escale = expf(log_scale[d0 + ty]);

    const float* xp = x     + (size_t)b * S_LEN * D_DIM;
    const float* op = omega + (size_t)b * S_LEN * D_DIM;
    float*       cp = ctx   + (size_t)b * S_LEN * FD;

    float c0 = 0.0f, c1 = 0.0f, c2 = 0.0f;

    for (int s0 = 0; s0 < S_LEN; s0 += 32) {
        xs[ty][tx] = xp[(size_t)(s0 + ty) * D_DIM + d0 + tx];
        os[ty][tx] = op[(size_t)(s0 + ty) * D_DIM + d0 + tx];
        __syncthreads();

        const float pos = (float)(s0 + tx + 1);
        float w = os[tx][ty] * escale * rsqrtf(pos);

        float pl = w;
        #pragma unroll
        for (int off = 1; off < 32; off <<= 1) {
            float t = __shfl_up_sync(0xffffffffu, pl, off);
            if (tx >= off) pl += t;
        }
        const float phi = c0 + pl;
        c0 += __shfl_sync(0xffffffffu, pl, 31);

        float sv, cv;
        sincosf(phi, &sv, &cv);
        const float xv  = xs[tx][ty];
        const float cmr = xv * cv;
        const float cmi = xv * sv;

        float pr = cmr;
        #pragma unroll
        for (int off = 1; off < 32; off <<= 1) {
            float t = __shfl_up_sync(0xffffffffu, pr, off);
            if (tx >= off) pr += t;
        }
        float pi = cmi;
        #pragma unroll
        for (int off = 1; off < 32; off <<= 1) {
            float t = __shfl_up_sync(0xffffffffu, pi, off);
            if (tx >= off) pi += t;
        }

        const float memr = (c1 + pr) / pos;
        const float memi = (c2 + pi) / pos;
        c1 += __shfl_sync(0xffffffffu, pr, 31);
        c2 += __shfl_sync(0xffffffffu, pi, 31);

        const float retr = memr * cv + memi * sv;
        const float reti = memi * cv - memr * sv;

        ob[0][tx][ty] = cmr;
        ob[1][tx][ty] = cmi;
        ob[2][tx][ty] = retr;
        ob[3][tx][ty] = reti;
        __syncthreads();

        const size_t ro = (size_t)(s0 + ty) * FD + d0 + tx;
        cp[ro]             = ob[0][ty][tx];
        cp[ro + D_DIM]     = ob[1][ty][tx];
        cp[ro + 2 * D_DIM] = ob[2][ty][tx];
        cp[ro + 3 * D_DIM] = ob[3][ty][tx];
    }
}

// ---------------------------------------------------------------------------
// LayerNorm over FD=4096; reads fp32 ctx, writes split bf16 hi/lo
// ---------------------------------------------------------------------------
__global__ __launch_bounds__(256)
void ln_split_kernel(const float* __restrict__ ctx, __nv_bfloat16* __restrict__ outh,
                     __nv_bfloat16* __restrict__ outl, const float* __restrict__ gamma,
                     const float* __restrict__ beta)
{
    __shared__ float buf[FD];
    __shared__ float red1[8], red2[8];

    const float* row = ctx + (size_t)blockIdx.x * FD;
    const size_t obase = (size_t)blockIdx.x * FD;
    const int tid = threadIdx.x;

    float s1 = 0.0f, s2 = 0.0f;
    #pragma unroll
    for (int i = 0; i < 4; i++) {
        const int idx = (tid + i * 256) * 4;
        float4 v = *(const float4*)(row + idx);
        *(float4*)(buf + idx) = v;
        s1 += v.x + v.y + v.z + v.w;
        s2 += v.x * v.x + v.y * v.y + v.z * v.z + v.w * v.w;
    }
    #pragma unroll
    for (int off = 16; off > 0; off >>= 1) {
        s1 += __shfl_down_sync(0xffffffffu, s1, off);
        s2 += __shfl_down_sync(0xffffffffu, s2, off);
    }
    if ((tid & 31) == 0) { red1[tid >> 5] = s1; red2[tid >> 5] = s2; }
    __syncthreads();
    if (tid < 32) {
        s1 = (tid < 8) ? red1[tid] : 0.0f;
        s2 = (tid < 8) ? red2[tid] : 0.0f;
        #pragma unroll
        for (int off = 4; off > 0; off >>= 1) {
            s1 += __shfl_down_sync(0xffffffffu, s1, off);
            s2 += __shfl_down_sync(0xffffffffu, s2, off);
        }
        if (tid == 0) { red1[0] = s1; red2[0] = s2; }
    }
    __syncthreads();

    const float mean = red1[0] * (1.0f / FD);
    const float var  = red2[0] * (1.0f / FD) - mean * mean;
    const float inv  = rsqrtf(var + 1e-5f);

    #pragma unroll
    for (int i = 0; i < 4; i++) {
        const int idx = (tid + i * 256) * 4;
        float4 v  = *(const float4*)(buf + idx);
        float4 ga = *(const float4*)(gamma + idx);
        float4 be = *(const float4*)(beta + idx);
        float r0 = (v.x - mean) * inv * ga.x + be.x;
        float r1 = (v.y - mean) * inv * ga.y + be.y;
        float r2 = (v.z - mean) * inv * ga.z + be.z;
        float r3 = (v.w - mean) * inv * ga.w + be.w;
        __nv_bfloat16 h0 = __float2bfloat16(r0), h1 = __float2bfloat16(r1);
        __nv_bfloat16 h2 = __float2bfloat16(r2), h3 = __float2bfloat16(r3);
        *(__nv_bfloat162*)(outh + obase + idx)     = __nv_bfloat162(h0, h1);
        *(__nv_bfloat162*)(outh + obase + idx + 2) = __nv_bfloat162(h2, h3);
        *(__nv_bfloat162*)(outl + obase + idx)     = __nv_bfloat162(
            __float2bfloat16(r0 - __bfloat162float(h0)), __float2bfloat16(r1 - __bfloat162float(h1)));
        *(__nv_bfloat162*)(outl + obase + idx + 2) = __nv_bfloat162(
            __float2bfloat16(r2 - __bfloat162float(h2)), __float2bfloat16(r3 - __bfloat162float(h3)));
    }
}

// ---------------------------------------------------------------------------
extern "C" void kernel_launch(void* const* d_in, const int* in_sizes, int n_in,
                              void* d_out, int out_size)
{
    const float* x         = (const float*)d_in[0];
    const float* W_omega   = (const float*)d_in[1];
    const float* b_omega   = (const float*)d_in[2];
    const float* log_scale = (const float*)d_in[3];
    const float* ln_gamma  = (const float*)d_in[4];
    const float* ln_beta   = (const float*)d_in[5];
    const float* W1        = (const float*)d_in[6];
    const float* b1        = (const float*)d_in[7];
    const float* W2        = (const float*)d_in[8];
    const float* b2        = (const float*)d_in[9];
    float* out = (float*)d_out;

    float *omega_p, *ctx_p;
    __nv_bfloat16 *xh, *xl, *w0h, *w0l, *w1h, *w1l, *w2h, *w2l, *ch, *cl, *h1h, *h1l;
    cudaGetSymbolAddress((void**)&omega_p, g_omega);
    cudaGetSymbolAddress((void**)&ctx_p,   g_ctx);
    cudaGetSymbolAddress((void**)&xh,  g_xh);  cudaGetSymbolAddress((void**)&xl,  g_xl);
    cudaGetSymbolAddress((void**)&w0h, g_w0h); cudaGetSymbolAddress((void**)&w0l, g_w0l);
    cudaGetSymbolAddress((void**)&w1h, g_w1h); cudaGetSymbolAddress((void**)&w1l, g_w1l);
    cudaGetSymbolAddress((void**)&w2h, g_w2h); cudaGetSymbolAddress((void**)&w2l, g_w2l);
    cudaGetSymbolAddress((void**)&ch,  g_ch);  cudaGetSymbolAddress((void**)&cl,  g_cl);
    cudaGetSymbolAddress((void**)&h1h, g_h1h); cudaGetSymbolAddress((void**)&h1l, g_h1l);

    cudaFuncSetAttribute(gemm_tc_kernel<0>, cudaFuncAttributeMaxDynamicSharedMemorySize, GEMM_DSM);
    cudaFuncSetAttribute(gemm_tc_kernel<1>, cudaFuncAttributeMaxDynamicSharedMemorySize, GEMM_DSM);
    cudaFuncSetAttribute(gemm_tc_kernel<2>, cudaFuncAttributeMaxDynamicSharedMemorySize, GEMM_DSM);

    auto launch_split = [&](const float* in, __nv_bfloat16* h, __nv_bfloat16* l, size_t n) {
        int n4 = (int)(n / 4);
        split_kernel<<<(n4 + 255) / 256, 256>>>(in, h, l, n4);
    };
    launch_split(x,       xh,  xl,  (size_t)NROWS * D_DIM);
    launch_split(W_omega, w0h, w0l, (size_t)D_DIM * D_DIM);
    launch_split(W1,      w1h, w1l, (size_t)HD * FD);
    launch_split(W2,      w2h, w2l, (size_t)D_DIM * HD);

    // 1) omega = x @ W_omega^T + b_omega
    gemm_tc_kernel<0><<<dim3(D_DIM / 128, NROWS / 128), 256, GEMM_DSM>>>(
        xh, xl, w0h, w0l, b_omega, nullptr, omega_p, nullptr, nullptr,
        NROWS, D_DIM, D_DIM);

    // 2) scans -> ctx fp32
    scan_kernel<<<dim3(D_DIM / 32, B_DIM), dim3(32, 32)>>>(x, omega_p, log_scale, ctx_p);

    // 3) LayerNorm -> split bf16 ctx
    ln_split_kernel<<<NROWS, 256>>>(ctx_p, ch, cl, ln_gamma, ln_beta);

    // 4) h1 = GELU(ctx @ W1^T + b1) -> split bf16
    gemm_tc_kernel<1><<<dim3(HD / 128, NROWS / 128), 256, GEMM_DSM>>>(
        ch, cl, w1h, w1l, b1, nullptr, nullptr, h1h, h1l,
        NROWS, HD, FD);

    // 5) out = x + h1 @ W2^T + b2
    gemm_tc_kernel<2><<<dim3(D_DIM / 128, NROWS / 128), 256, GEMM_DSM>>>(
        h1h, h1l, w2h, w2l, b2, x, out, nullptr, nullptr,
        NROWS, D_DIM, HD);
}

// round 4
// speedup vs baseline: 5.7102x; 2.1716x over previous
#include <cuda_runtime.h>
#include <cuda_bf16.h>
#include <cuda_fp16.h>
#include <math.h>
#include <stdint.h>

// Shapes fixed: B=4, S=4096, D=1024
static constexpr int S_LEN = 4096;
static constexpr int D_DIM = 1024;
static constexpr int B_DIM = 4;
static constexpr int FD    = 4 * D_DIM;     // 4096
static constexpr int HD    = 2 * D_DIM;     // 2048
static constexpr int NROWS = B_DIM * S_LEN; // 16384

// ---------------- scratch (device globals; no allocs allowed) ----------------
__device__ float g_omega[(size_t)NROWS * D_DIM];   // 64 MB
__device__ float g_ctx  [(size_t)NROWS * FD];      // 256 MB
__device__ __nv_bfloat16 g_xh [(size_t)NROWS * D_DIM];
__device__ __nv_bfloat16 g_xl [(size_t)NROWS * D_DIM];
__device__ __nv_bfloat16 g_w0h[(size_t)D_DIM * D_DIM];
__device__ __nv_bfloat16 g_w0l[(size_t)D_DIM * D_DIM];
__device__ __half g_w1f[(size_t)HD * FD];          // 16 MB
__device__ __half g_w2f[(size_t)D_DIM * HD];       //  4 MB
__device__ __half g_cf [(size_t)NROWS * FD];       // 128 MB (LN output)
__device__ __half g_h1f[(size_t)NROWS * HD];       //  64 MB

// ---------------- PTX helpers (stable ISA only) ----------------
__device__ __forceinline__ uint32_t smem_u32(const void* p) {
    uint32_t a;
    asm("{ .reg .u64 t; cvta.to.shared.u64 t, %1; cvt.u32.u64 %0, t; }" : "=r"(a) : "l"(p));
    return a;
}
__device__ __forceinline__ void cp_async16(uint32_t saddr, const void* gptr) {
    asm volatile("cp.async.cg.shared.global [%0], [%1], 16;" :: "r"(saddr), "l"(gptr));
}
__device__ __forceinline__ void cp_commit() { asm volatile("cp.async.commit_group;" ::: "memory"); }
template <int N> __device__ __forceinline__ void cp_wait() {
    asm volatile("cp.async.wait_group %0;" :: "n"(N) : "memory");
}

#define LDMX4(r0, r1, r2, r3, addr)                                              \
    asm volatile("ldmatrix.sync.aligned.m8n8.x4.shared.b16 {%0,%1,%2,%3}, [%4];" \
        : "=r"(r0), "=r"(r1), "=r"(r2), "=r"(r3) : "r"(addr))

#define MMA16816_BF(d, a, b0, b1)                                                \
    asm volatile("mma.sync.aligned.m16n8k16.row.col.f32.bf16.bf16.f32 "          \
        "{%0,%1,%2,%3}, {%4,%5,%6,%7}, {%8,%9}, {%0,%1,%2,%3};"                  \
        : "+f"((d)[0]), "+f"((d)[1]), "+f"((d)[2]), "+f"((d)[3])                 \
        : "r"((a)[0]), "r"((a)[1]), "r"((a)[2]), "r"((a)[3]), "r"(b0), "r"(b1))

#define MMA16816_F16(d, a, b0, b1)                                               \
    asm volatile("mma.sync.aligned.m16n8k16.row.col.f32.f16.f16.f32 "            \
        "{%0,%1,%2,%3}, {%4,%5,%6,%7}, {%8,%9}, {%0,%1,%2,%3};"                  \
        : "+f"((d)[0]), "+f"((d)[1]), "+f"((d)[2]), "+f"((d)[3])                 \
        : "r"((a)[0]), "r"((a)[1]), "r"((a)[2]), "r"((a)[3]), "r"(b0), "r"(b1))

// ===========================================================================
// 3-term split-bf16 GEMM (GEMM1 only: phase-sensitive). C = A*B^T + bias, fp32.
// ===========================================================================
static constexpr int TILE_B    = 128 * 128;          // 16 KB bf16 128x64 tile
static constexpr int STAGE_B3  = 4 * TILE_B;         // Ah, Al, Bh, Bl
static constexpr int NSTAGE3   = 3;
static constexpr int GEMM_DSM3 = NSTAGE3 * STAGE_B3; // 192 KB

__global__ __launch_bounds__(256, 1)
void gemm_bf16x3_kernel(const __nv_bfloat16* __restrict__ Ah, const __nv_bfloat16* __restrict__ Al,
                        const __nv_bfloat16* __restrict__ Bh, const __nv_bfloat16* __restrict__ Bl,
                        const float* __restrict__ bias, float* __restrict__ outf,
                        int M, int N, int K)
{
    extern __shared__ __align__(1024) unsigned char dsm[];
    const int tid = threadIdx.x;
    const int wid = tid >> 5;
    const int lid = tid & 31;
    const int m0 = blockIdx.y * 128;
    const int n0 = blockIdx.x * 128;
    const uint32_t dsm_b = smem_u32(dsm);

    const int warpM = wid >> 2, warpN = wid & 3;
    const int rl = lid & 15, chh = lid >> 4;

    const __nv_bfloat16* tiles[4] = {
        Ah + (size_t)m0 * K, Al + (size_t)m0 * K,
        Bh + (size_t)n0 * K, Bl + (size_t)n0 * K };

    const int nchunk = K >> 6;

    auto load_chunk = [&](int chunk) {
        const uint32_t sb = dsm_b + (chunk % NSTAGE3) * STAGE_B3;
        const int koff = chunk << 6;
        #pragma unroll
        for (int t = 0; t < 4; t++) {
            #pragma unroll
            for (int i = 0; i < 4; i++) {
                const int u = i * 256 + tid;
                const int row = u >> 3, c = u & 7;
                const void* gp = tiles[t] + (size_t)row * K + koff + c * 8;
                const uint32_t sa = sb + t * TILE_B + row * 128 + ((c ^ (row & 7)) << 4);
                cp_async16(sa, gp);
            }
        }
        cp_commit();
    };

    float acc[4][4][4];
    #pragma unroll
    for (int mi = 0; mi < 4; mi++)
        #pragma unroll
        for (int ni = 0; ni < 4; ni++)
            #pragma unroll
            for (int r = 0; r < 4; r++) acc[mi][ni][r] = 0.0f;

    load_chunk(0);
    load_chunk(1);

    for (int c = 0; c < nchunk; c++) {
        if (c < nchunk - 1) cp_wait<1>(); else cp_wait<0>();
        __syncthreads();
        if (c + 2 < nchunk) load_chunk(c + 2);

        const uint32_t st = dsm_b + (c % NSTAGE3) * STAGE_B3;
        #pragma unroll
        for (int ks = 0; ks < 4; ks++) {
            const int kchunk = (ks << 1) | chh;
            uint32_t ah[4][4], al[4][4], bh[2][4], bl[2][4];
            #pragma unroll
            for (int mi = 0; mi < 4; mi++) {
                const int row = warpM * 64 + mi * 16 + rl;
                const uint32_t ad = st + row * 128 + ((kchunk ^ (row & 7)) << 4);
                LDMX4(ah[mi][0], ah[mi][1], ah[mi][2], ah[mi][3], ad);
                LDMX4(al[mi][0], al[mi][1], al[mi][2], al[mi][3], ad + TILE_B);
            }
            #pragma unroll
            for (int nj = 0; nj < 2; nj++) {
                const int row = warpN * 32 + nj * 16 + rl;
                const uint32_t bd = st + 2 * TILE_B + row * 128 + ((kchunk ^ (row & 7)) << 4);
                LDMX4(bh[nj][0], bh[nj][1], bh[nj][2], bh[nj][3], bd);
                LDMX4(bl[nj][0], bl[nj][1], bl[nj][2], bl[nj][3], bd + TILE_B);
            }
            #pragma unroll
            for (int mi = 0; mi < 4; mi++)
                #pragma unroll
                for (int ni = 0; ni < 4; ni++) {
                    const int nj = ni >> 1, sel = ni & 1;
                    MMA16816_BF(acc[mi][ni], ah[mi], bh[nj][sel], bh[nj][2 + sel]);
                    MMA16816_BF(acc[mi][ni], ah[mi], bl[nj][sel], bl[nj][2 + sel]);
                    MMA16816_BF(acc[mi][ni], al[mi], bh[nj][sel], bh[nj][2 + sel]);
                }
        }
    }

    const int g = lid >> 2, q = lid & 3;
    #pragma unroll
    for (int mi = 0; mi < 4; mi++)
        #pragma unroll
        for (int ni = 0; ni < 4; ni++) {
            const int row = m0 + warpM * 64 + mi * 16 + g;
            const int col = n0 + warpN * 32 + ni * 8 + q * 2;
            const float2 bb = *(const float2*)(bias + col);
            const size_t o0 = (size_t)row * N + col;
            const size_t o1 = (size_t)(row + 8) * N + col;
            *(float2*)(outf + o0) = make_float2(acc[mi][ni][0] + bb.x, acc[mi][ni][1] + bb.y);
            *(float2*)(outf + o1) = make_float2(acc[mi][ni][2] + bb.x, acc[mi][ni][3] + bb.y);
        }
}

// ===========================================================================
// 1-term fp16 GEMM: C[M,N] = A[M,K]*B[N,K]^T + bias.
// EPI 1: GELU -> fp16 out.  EPI 2: + res -> fp32 out.
// Stage = A+B tiles (32 KB), NSTAGE=3 (96 KB) -> 2 CTAs/SM.
// ===========================================================================
static constexpr int STAGE_BF  = 2 * TILE_B;          // 32 KB
static constexpr int NSTAGEF   = 3;
static constexpr int GEMM_DSMF = NSTAGEF * STAGE_BF;  // 96 KB

template <int EPI>
__global__ __launch_bounds__(256, 2)
void gemm_f16_kernel(const __half* __restrict__ A, const __half* __restrict__ B,
                     const float* __restrict__ bias, const float* __restrict__ res,
                     float* __restrict__ outf, __half* __restrict__ outh,
                     int M, int N, int K)
{
    extern __shared__ __align__(1024) unsigned char dsm[];
    const int tid = threadIdx.x;
    const int wid = tid >> 5;
    const int lid = tid & 31;
    const int m0 = blockIdx.y * 128;
    const int n0 = blockIdx.x * 128;
    const uint32_t dsm_b = smem_u32(dsm);

    const int warpM = wid >> 2, warpN = wid & 3;
    const int rl = lid & 15, chh = lid >> 4;

    const __half* At = A + (size_t)m0 * K;
    const __half* Bt = B + (size_t)n0 * K;

    const int nchunk = K >> 6;

    auto load_chunk = [&](int chunk) {
        const uint32_t sb = dsm_b + (chunk % NSTAGEF) * STAGE_BF;
        const int koff = chunk << 6;
        #pragma unroll
        for (int i = 0; i < 8; i++) {
            const int u = i * 256 + tid;           // 0..2047
            const int t = u >> 10;                 // 0=A, 1=B
            const int v = u & 1023;
            const int row = v >> 3, c = v & 7;
            const __half* g = t ? Bt : At;
            const void* gp = g + (size_t)row * K + koff + c * 8;
            const uint32_t sa = sb + t * TILE_B + row * 128 + ((c ^ (row & 7)) << 4);
            cp_async16(sa, gp);
        }
        cp_commit();
    };

    float acc[4][4][4];
    #pragma unroll
    for (int mi = 0; mi < 4; mi++)
        #pragma unroll
        for (int ni = 0; ni < 4; ni++)
            #pragma unroll
            for (int r = 0; r < 4; r++) acc[mi][ni][r] = 0.0f;

    load_chunk(0);
    load_chunk(1);

    for (int c = 0; c < nchunk; c++) {
        if (c < nchunk - 1) cp_wait<1>(); else cp_wait<0>();
        __syncthreads();
        if (c + 2 < nchunk) load_chunk(c + 2);

        const uint32_t st = dsm_b + (c % NSTAGEF) * STAGE_BF;
        #pragma unroll
        for (int ks = 0; ks < 4; ks++) {
            const int kchunk = (ks << 1) | chh;
            uint32_t a[4][4], b[2][4];
            #pragma unroll
            for (int mi = 0; mi < 4; mi++) {
                const int row = warpM * 64 + mi * 16 + rl;
                const uint32_t ad = st + row * 128 + ((kchunk ^ (row & 7)) << 4);
                LDMX4(a[mi][0], a[mi][1], a[mi][2], a[mi][3], ad);
            }
            #pragma unroll
            for (int nj = 0; nj < 2; nj++) {
                const int row = warpN * 32 + nj * 16 + rl;
                const uint32_t bd = st + TILE_B + row * 128 + ((kchunk ^ (row & 7)) << 4);
                LDMX4(b[nj][0], b[nj][1], b[nj][2], b[nj][3], bd);
            }
            #pragma unroll
            for (int mi = 0; mi < 4; mi++)
                #pragma unroll
                for (int ni = 0; ni < 4; ni++) {
                    const int nj = ni >> 1, sel = ni & 1;
                    MMA16816_F16(acc[mi][ni], a[mi], b[nj][sel], b[nj][2 + sel]);
                }
        }
    }

    const int g = lid >> 2, q = lid & 3;
    #pragma unroll
    for (int mi = 0; mi < 4; mi++)
        #pragma unroll
        for (int ni = 0; ni < 4; ni++) {
            const int row = m0 + warpM * 64 + mi * 16 + g;
            const int col = n0 + warpN * 32 + ni * 8 + q * 2;
            const float2 bb = *(const float2*)(bias + col);
            float v[4];
            v[0] = acc[mi][ni][0] + bb.x;
            v[1] = acc[mi][ni][1] + bb.y;
            v[2] = acc[mi][ni][2] + bb.x;
            v[3] = acc[mi][ni][3] + bb.y;
            const size_t o0 = (size_t)row * N + col;
            const size_t o1 = (size_t)(row + 8) * N + col;
            if (EPI == 1) {
                #pragma unroll
                for (int r = 0; r < 4; r++)
                    v[r] = 0.5f * v[r] * (1.0f + erff(v[r] * 0.70710678118654752f));
                *(__half2*)(outh + o0) = __floats2half2_rn(v[0], v[1]);
                *(__half2*)(outh + o1) = __floats2half2_rn(v[2], v[3]);
            } else {
                const float2 r0 = *(const float2*)(res + o0);
                const float2 r1 = *(const float2*)(res + o1);
                *(float2*)(outf + o0) = make_float2(v[0] + r0.x, v[1] + r0.y);
                *(float2*)(outf + o1) = make_float2(v[2] + r1.x, v[3] + r1.y);
            }
        }
}

// ---------------------------------------------------------------------------
// fp32 -> bf16 hi/lo split (GEMM1 operands)
// ---------------------------------------------------------------------------
__global__ __launch_bounds__(256)
void split_kernel(const float* __restrict__ in, __nv_bfloat16* __restrict__ hi,
                  __nv_bfloat16* __restrict__ lo, int n4)
{
    int i = blockIdx.x * blockDim.x + threadIdx.x;
    if (i >= n4) return;
    float4 v = ((const float4*)in)[i];
    __nv_bfloat16 h0 = __float2bfloat16(v.x), h1 = __float2bfloat16(v.y);
    __nv_bfloat16 h2 = __float2bfloat16(v.z), h3 = __float2bfloat16(v.w);
    __nv_bfloat162* hp = (__nv_bfloat162*)hi;
    __nv_bfloat162* lp = (__nv_bfloat162*)lo;
    hp[2 * i]     = __nv_bfloat162(h0, h1);
    hp[2 * i + 1] = __nv_bfloat162(h2, h3);
    lp[2 * i]     = __nv_bfloat162(__float2bfloat16(v.x - __bfloat162float(h0)),
                                   __float2bfloat16(v.y - __bfloat162float(h1)));
    lp[2 * i + 1] = __nv_bfloat162(__float2bfloat16(v.z - __bfloat162float(h2)),
                                   __float2bfloat16(v.w - __bfloat162float(h3)));
}

// fp32 -> fp16 convert (W1, W2)
__global__ __launch_bounds__(256)
void cvt_f16_kernel(const float* __restrict__ in, __half* __restrict__ o, int n4)
{
    int i = blockIdx.x * blockDim.x + threadIdx.x;
    if (i >= n4) return;
    float4 v = ((const float4*)in)[i];
    __half2* op = (__half2*)o;
    op[2 * i]     = __floats2half2_rn(v.x, v.y);
    op[2 * i + 1] = __floats2half2_rn(v.z, v.w);
}

// ---------------------------------------------------------------------------
// Fused sequential scans (validated)
// ---------------------------------------------------------------------------
__global__ __launch_bounds__(1024)
void scan_kernel(const float* __restrict__ x, const float* __restrict__ omega,
                 const float* __restrict__ log_scale, float* __restrict__ ctx)
{
    __shared__ float xs[32][33];
    __shared__ float os[32][33];
    __shared__ float ob[4][32][33];

    const int b  = blockIdx.y;
    const int d0 = blockIdx.x * 32;
    const int tx = threadIdx.x;
    const int ty = threadIdx.y;

    const float escale = expf(log_scale[d0 + ty]);

    const float* xp = x     + (size_t)b * S_LEN * D_DIM;
    const float* op = omega + (size_t)b * S_LEN * D_DIM;
    float*       cp = ctx   + (size_t)b * S_LEN * FD;

    float c0 = 0.0f, c1 = 0.0f, c2 = 0.0f;

    for (int s0 = 0; s0 < S_LEN; s0 += 32) {
        xs[ty][tx] = xp[(size_t)(s0 + ty) * D_DIM + d0 + tx];
        os[ty][tx] = op[(size_t)(s0 + ty) * D_DIM + d0 + tx];
        __syncthreads();

        const float pos = (float)(s0 + tx + 1);
        float w = os[tx][ty] * escale * rsqrtf(pos);

        float pl = w;
        #pragma unroll
        for (int off = 1; off < 32; off <<= 1) {
            float t = __shfl_up_sync(0xffffffffu, pl, off);
            if (tx >= off) pl += t;
        }
        const float phi = c0 + pl;
        c0 += __shfl_sync(0xffffffffu, pl, 31);

        float sv, cv;
        sincosf(phi, &sv, &cv);
        const float xv  = xs[tx][ty];
        const float cmr = xv * cv;
        const float cmi = xv * sv;

        float pr = cmr;
        #pragma unroll
        for (int off = 1; off < 32; off <<= 1) {
            float t = __shfl_up_sync(0xffffffffu, pr, off);
            if (tx >= off) pr += t;
        }
        float pi = cmi;
        #pragma unroll
        for (int off = 1; off < 32; off <<= 1) {
            float t = __shfl_up_sync(0xffffffffu, pi, off);
            if (tx >= off) pi += t;
        }

        const float memr = (c1 + pr) / pos;
        const float memi = (c2 + pi) / pos;
        c1 += __shfl_sync(0xffffffffu, pr, 31);
        c2 += __shfl_sync(0xffffffffu, pi, 31);

        const float retr = memr * cv + memi * sv;
        const float reti = memi * cv - memr * sv;

        ob[0][tx][ty] = cmr;
        ob[1][tx][ty] = cmi;
        ob[2][tx][ty] = retr;
        ob[3][tx][ty] = reti;
        __syncthreads();

        const size_t ro = (size_t)(s0 + ty) * FD + d0 + tx;
        cp[ro]             = ob[0][ty][tx];
        cp[ro + D_DIM]     = ob[1][ty][tx];
        cp[ro + 2 * D_DIM] = ob[2][ty][tx];
        cp[ro + 3 * D_DIM] = ob[3][ty][tx];
    }
}

// ---------------------------------------------------------------------------
// LayerNorm over FD=4096; reads fp32 ctx, writes fp16
// ---------------------------------------------------------------------------
__global__ __launch_bounds__(256)
void ln_f16_kernel(const float* __restrict__ ctx, __half* __restrict__ outh,
                   const float* __restrict__ gamma, const float* __restrict__ beta)
{
    __shared__ float buf[FD];
    __shared__ float red1[8], red2[8];

    const float* row = ctx + (size_t)blockIdx.x * FD;
    const size_t obase = (size_t)blockIdx.x * FD;
    const int tid = threadIdx.x;

    float s1 = 0.0f, s2 = 0.0f;
    #pragma unroll
    for (int i = 0; i < 4; i++) {
        const int idx = (tid + i * 256) * 4;
        float4 v = *(const float4*)(row + idx);
        *(float4*)(buf + idx) = v;
        s1 += v.x + v.y + v.z + v.w;
        s2 += v.x * v.x + v.y * v.y + v.z * v.z + v.w * v.w;
    }
    #pragma unroll
    for (int off = 16; off > 0; off >>= 1) {
        s1 += __shfl_down_sync(0xffffffffu, s1, off);
        s2 += __shfl_down_sync(0xffffffffu, s2, off);
    }
    if ((tid & 31) == 0) { red1[tid >> 5] = s1; red2[tid >> 5] = s2; }
    __syncthreads();
    if (tid < 32) {
        s1 = (tid < 8) ? red1[tid] : 0.0f;
        s2 = (tid < 8) ? red2[tid] : 0.0f;
        #pragma unroll
        for (int off = 4; off > 0; off >>= 1) {
            s1 += __shfl_down_sync(0xffffffffu, s1, off);
            s2 += __shfl_down_sync(0xffffffffu, s2, off);
        }
        if (tid == 0) { red1[0] = s1; red2[0] = s2; }
    }
    __syncthreads();

    const float mean = red1[0] * (1.0f / FD);
    const float var  = red2[0] * (1.0f / FD) - mean * mean;
    const float inv  = rsqrtf(var + 1e-5f);

    #pragma unroll
    for (int i = 0; i < 4; i++) {
        const int idx = (tid + i * 256) * 4;
        float4 v  = *(const float4*)(buf + idx);
        float4 ga = *(const float4*)(gamma + idx);
        float4 be = *(const float4*)(beta + idx);
        float r0 = (v.x - mean) * inv * ga.x + be.x;
        float r1 = (v.y - mean) * inv * ga.y + be.y;
        float r2 = (v.z - mean) * inv * ga.z + be.z;
        float r3 = (v.w - mean) * inv * ga.w + be.w;
        *(__half2*)(outh + obase + idx)     = __floats2half2_rn(r0, r1);
        *(__half2*)(outh + obase + idx + 2) = __floats2half2_rn(r2, r3);
    }
}

// ---------------------------------------------------------------------------
extern "C" void kernel_launch(void* const* d_in, const int* in_sizes, int n_in,
                              void* d_out, int out_size)
{
    const float* x         = (const float*)d_in[0];
    const float* W_omega   = (const float*)d_in[1];
    const float* b_omega   = (const float*)d_in[2];
    const float* log_scale = (const float*)d_in[3];
    const float* ln_gamma  = (const float*)d_in[4];
    const float* ln_beta   = (const float*)d_in[5];
    const float* W1        = (const float*)d_in[6];
    const float* b1        = (const float*)d_in[7];
    const float* W2        = (const float*)d_in[8];
    const float* b2        = (const float*)d_in[9];
    float* out = (float*)d_out;

    float *omega_p, *ctx_p;
    __nv_bfloat16 *xh, *xl, *w0h, *w0l;
    __half *w1f, *w2f, *cf, *h1f;
    cudaGetSymbolAddress((void**)&omega_p, g_omega);
    cudaGetSymbolAddress((void**)&ctx_p,   g_ctx);
    cudaGetSymbolAddress((void**)&xh,  g_xh);  cudaGetSymbolAddress((void**)&xl,  g_xl);
    cudaGetSymbolAddress((void**)&w0h, g_w0h); cudaGetSymbolAddress((void**)&w0l, g_w0l);
    cudaGetSymbolAddress((void**)&w1f, g_w1f); cudaGetSymbolAddress((void**)&w2f, g_w2f);
    cudaGetSymbolAddress((void**)&cf,  g_cf);  cudaGetSymbolAddress((void**)&h1f, g_h1f);

    cudaFuncSetAttribute(gemm_bf16x3_kernel, cudaFuncAttributeMaxDynamicSharedMemorySize, GEMM_DSM3);
    cudaFuncSetAttribute(gemm_f16_kernel<1>, cudaFuncAttributeMaxDynamicSharedMemorySize, GEMM_DSMF);
    cudaFuncSetAttribute(gemm_f16_kernel<2>, cudaFuncAttributeMaxDynamicSharedMemorySize, GEMM_DSMF);

    // operand conversions
    {
        int n4 = NROWS * D_DIM / 4;
        split_kernel<<<(n4 + 255) / 256, 256>>>(x, xh, xl, n4);
        n4 = D_DIM * D_DIM / 4;
        split_kernel<<<(n4 + 255) / 256, 256>>>(W_omega, w0h, w0l, n4);
        n4 = HD * FD / 4;
        cvt_f16_kernel<<<(n4 + 255) / 256, 256>>>(W1, w1f, n4);
        n4 = D_DIM * HD / 4;
        cvt_f16_kernel<<<(n4 + 255) / 256, 256>>>(W2, w2f, n4);
    }

    // 1) omega = x @ W_omega^T + b_omega   (3-term bf16: phase-sensitive)
    gemm_bf16x3_kernel<<<dim3(D_DIM / 128, NROWS / 128), 256, GEMM_DSM3>>>(
        xh, xl, w0h, w0l, b_omega, omega_p, NROWS, D_DIM, D_DIM);

    // 2) scans -> ctx fp32
    scan_kernel<<<dim3(D_DIM / 32, B_DIM), dim3(32, 32)>>>(x, omega_p, log_scale, ctx_p);

    // 3) LayerNorm -> fp16 ctx
    ln_f16_kernel<<<NROWS, 256>>>(ctx_p, cf, ln_gamma, ln_beta);

    // 4) h1 = GELU(ctx @ W1^T + b1) -> fp16
    gemm_f16_kernel<1><<<dim3(HD / 128, NROWS / 128), 256, GEMM_DSMF>>>(
        cf, w1f, b1, nullptr, nullptr, h1f, NROWS, HD, FD);

    // 5) out = x + h1 @ W2^T + b2
    gemm_f16_kernel<2><<<dim3(D_DIM / 128, NROWS / 128), 256, GEMM_DSMF>>>(
        h1f, w2f, b2, x, out, nullptr, NROWS, D_DIM, HD);
}

// round 5
// speedup vs baseline: 6.9923x; 1.2245x over previous
#include <cuda_runtime.h>
#include <cuda_fp16.h>
#include <math.h>
#include <stdint.h>

// Shapes fixed: B=4, S=4096, D=1024
static constexpr int S_LEN = 4096;
static constexpr int D_DIM = 1024;
static constexpr int B_DIM = 4;
static constexpr int FD    = 4 * D_DIM;     // 4096
static constexpr int HD    = 2 * D_DIM;     // 2048
static constexpr int NROWS = B_DIM * S_LEN; // 16384
static constexpr int NDBLK = D_DIM / 32;    // 32 scan d-blocks

// ---------------- scratch (device globals; no allocs allowed) ----------------
__device__ __half g_xf  [(size_t)NROWS * D_DIM];   // 32 MB  x fp16
__device__ __half g_w0f [(size_t)D_DIM * D_DIM];   //  2 MB  W_omega fp16
__device__ __half g_omega[(size_t)NROWS * D_DIM];  // 32 MB  omega fp16
__device__ __half g_cf  [(size_t)NROWS * FD];      // 128 MB raw ctx fp16
__device__ __half g_w1g [(size_t)HD * FD];         // 16 MB  W1*gamma fp16
__device__ __half g_w2f [(size_t)D_DIM * HD];      //  4 MB  W2 fp16
__device__ __half g_h1f [(size_t)NROWS * HD];      // 64 MB  GELU output fp16
__device__ float  g_rs  [(size_t)NDBLK * NROWS];   //  2 MB  partial row sums
__device__ float  g_rs2 [(size_t)NDBLK * NROWS];   //  2 MB  partial row sumsq
__device__ float  g_mu  [NROWS];
__device__ float  g_inv [NROWS];
__device__ float  g_r1  [HD];                      // sum_d gamma*W1
__device__ float  g_r2  [HD];                      // sum_d beta*W1

// ---------------- PTX helpers (stable ISA only) ----------------
__device__ __forceinline__ uint32_t smem_u32(const void* p) {
    uint32_t a;
    asm("{ .reg .u64 t; cvta.to.shared.u64 t, %1; cvt.u32.u64 %0, t; }" : "=r"(a) : "l"(p));
    return a;
}
__device__ __forceinline__ void cp_async16(uint32_t saddr, const void* gptr) {
    asm volatile("cp.async.cg.shared.global [%0], [%1], 16;" :: "r"(saddr), "l"(gptr));
}
__device__ __forceinline__ void cp_commit() { asm volatile("cp.async.commit_group;" ::: "memory"); }
template <int N> __device__ __forceinline__ void cp_wait() {
    asm volatile("cp.async.wait_group %0;" :: "n"(N) : "memory");
}

#define LDMX4(r0, r1, r2, r3, addr)                                              \
    asm volatile("ldmatrix.sync.aligned.m8n8.x4.shared.b16 {%0,%1,%2,%3}, [%4];" \
        : "=r"(r0), "=r"(r1), "=r"(r2), "=r"(r3) : "r"(addr))

#define MMA16816_F16(d, a, b0, b1)                                               \
    asm volatile("mma.sync.aligned.m16n8k16.row.col.f32.f16.f16.f32 "            \
        "{%0,%1,%2,%3}, {%4,%5,%6,%7}, {%8,%9}, {%0,%1,%2,%3};"                  \
        : "+f"((d)[0]), "+f"((d)[1]), "+f"((d)[2]), "+f"((d)[3])                 \
        : "r"((a)[0]), "r"((a)[1]), "r"((a)[2]), "r"((a)[3]), "r"(b0), "r"(b1))

// ===========================================================================
// fp16 GEMM: C[M,N] = A[M,K]*B[N,K]^T.  128x128 tile, BK=64, 3-stage cp.async,
// 8 warps (2x4), warp 64x32, mma.sync.m16n8k16.
// EPI 0: + bias           -> f16 out            (GEMM1: omega)
// EPI 1: LN-affine + GELU -> f16 out            (GEMM2, fused LayerNorm)
// EPI 2: + bias + res     -> fp32 out           (GEMM3, residual)
// ===========================================================================
static constexpr int TILE_B    = 128 * 128;           // 16 KB f16 128x64 tile
static constexpr int STAGE_BF  = 2 * TILE_B;          // 32 KB
static constexpr int NSTAGEF   = 3;
static constexpr int GEMM_DSMF = NSTAGEF * STAGE_BF;  // 96 KB

template <int EPI>
__global__ __launch_bounds__(256, 2)
void gemm_f16_kernel(const __half* __restrict__ A, const __half* __restrict__ B,
                     const float* __restrict__ bias, const float* __restrict__ res,
                     const float* __restrict__ mu, const float* __restrict__ inv,
                     const float* __restrict__ r1, const float* __restrict__ r2,
                     float* __restrict__ outf, __half* __restrict__ outh,
                     int M, int N, int K)
{
    extern __shared__ __align__(1024) unsigned char dsm[];
    const int tid = threadIdx.x;
    const int wid = tid >> 5;
    const int lid = tid & 31;
    const int m0 = blockIdx.y * 128;
    const int n0 = blockIdx.x * 128;
    const uint32_t dsm_b = smem_u32(dsm);

    const int warpM = wid >> 2, warpN = wid & 3;
    const int rl = lid & 15, chh = lid >> 4;

    const __half* At = A + (size_t)m0 * K;
    const __half* Bt = B + (size_t)n0 * K;

    const int nchunk = K >> 6;

    auto load_chunk = [&](int chunk) {
        const uint32_t sb = dsm_b + (chunk % NSTAGEF) * STAGE_BF;
        const int koff = chunk << 6;
        #pragma unroll
        for (int i = 0; i < 8; i++) {
            const int u = i * 256 + tid;           // 0..2047
            const int t = u >> 10;                 // 0=A, 1=B
            const int v = u & 1023;
            const int row = v >> 3, c = v & 7;
            const __half* g = t ? Bt : At;
            const void* gp = g + (size_t)row * K + koff + c * 8;
            const uint32_t sa = sb + t * TILE_B + row * 128 + ((c ^ (row & 7)) << 4);
            cp_async16(sa, gp);
        }
        cp_commit();
    };

    float acc[4][4][4];
    #pragma unroll
    for (int mi = 0; mi < 4; mi++)
        #pragma unroll
        for (int ni = 0; ni < 4; ni++)
            #pragma unroll
            for (int r = 0; r < 4; r++) acc[mi][ni][r] = 0.0f;

    load_chunk(0);
    load_chunk(1);

    for (int c = 0; c < nchunk; c++) {
        if (c < nchunk - 1) cp_wait<1>(); else cp_wait<0>();
        __syncthreads();
        if (c + 2 < nchunk) load_chunk(c + 2);

        const uint32_t st = dsm_b + (c % NSTAGEF) * STAGE_BF;
        #pragma unroll
        for (int ks = 0; ks < 4; ks++) {
            const int kchunk = (ks << 1) | chh;
            uint32_t a[4][4], b[2][4];
            #pragma unroll
            for (int mi = 0; mi < 4; mi++) {
                const int row = warpM * 64 + mi * 16 + rl;
                const uint32_t ad = st + row * 128 + ((kchunk ^ (row & 7)) << 4);
                LDMX4(a[mi][0], a[mi][1], a[mi][2], a[mi][3], ad);
            }
            #pragma unroll
            for (int nj = 0; nj < 2; nj++) {
                const int row = warpN * 32 + nj * 16 + rl;
                const uint32_t bd = st + TILE_B + row * 128 + ((kchunk ^ (row & 7)) << 4);
                LDMX4(b[nj][0], b[nj][1], b[nj][2], b[nj][3], bd);
            }
            #pragma unroll
            for (int mi = 0; mi < 4; mi++)
                #pragma unroll
                for (int ni = 0; ni < 4; ni++) {
                    const int nj = ni >> 1, sel = ni & 1;
                    MMA16816_F16(acc[mi][ni], a[mi], b[nj][sel], b[nj][2 + sel]);
                }
        }
    }

    const int g = lid >> 2, q = lid & 3;
    #pragma unroll
    for (int mi = 0; mi < 4; mi++)
        #pragma unroll
        for (int ni = 0; ni < 4; ni++) {
            const int row = m0 + warpM * 64 + mi * 16 + g;
            const int col = n0 + warpN * 32 + ni * 8 + q * 2;
            const size_t o0 = (size_t)row * N + col;
            const size_t o1 = (size_t)(row + 8) * N + col;
            float v[4];
            if (EPI == 1) {
                // fused LayerNorm affine: inv*acc - inv*mu*r1[n] + r2[n] + bias[n]
                const float2 rr1 = *(const float2*)(r1 + col);
                const float2 rr2 = *(const float2*)(r2 + col);
                const float2 bb  = *(const float2*)(bias + col);
                const float i0 = inv[row],     m0v = mu[row];
                const float i1 = inv[row + 8], m1v = mu[row + 8];
                v[0] = i0 * acc[mi][ni][0] - i0 * m0v * rr1.x + rr2.x + bb.x;
                v[1] = i0 * acc[mi][ni][1] - i0 * m0v * rr1.y + rr2.y + bb.y;
                v[2] = i1 * acc[mi][ni][2] - i1 * m1v * rr1.x + rr2.x + bb.x;
                v[3] = i1 * acc[mi][ni][3] - i1 * m1v * rr1.y + rr2.y + bb.y;
                #pragma unroll
                for (int r = 0; r < 4; r++)
                    v[r] = 0.5f * v[r] * (1.0f + erff(v[r] * 0.70710678118654752f));
                *(__half2*)(outh + o0) = __floats2half2_rn(v[0], v[1]);
                *(__half2*)(outh + o1) = __floats2half2_rn(v[2], v[3]);
            } else {
                const float2 bb = *(const float2*)(bias + col);
                v[0] = acc[mi][ni][0] + bb.x;
                v[1] = acc[mi][ni][1] + bb.y;
                v[2] = acc[mi][ni][2] + bb.x;
                v[3] = acc[mi][ni][3] + bb.y;
                if (EPI == 2) {
                    const float2 q0 = *(const float2*)(res + o0);
                    const float2 q1 = *(const float2*)(res + o1);
                    *(float2*)(outf + o0) = make_float2(v[0] + q0.x, v[1] + q0.y);
                    *(float2*)(outf + o1) = make_float2(v[2] + q1.x, v[3] + q1.y);
                } else {
                    *(__half2*)(outh + o0) = __floats2half2_rn(v[0], v[1]);
                    *(__half2*)(outh + o1) = __floats2half2_rn(v[2], v[3]);
                }
            }
        }
}

// ---------------------------------------------------------------------------
// fp32 -> fp16 convert
// ---------------------------------------------------------------------------
__global__ __launch_bounds__(256)
void cvt_f16_kernel(const float* __restrict__ in, __half* __restrict__ o, int n4)
{
    int i = blockIdx.x * blockDim.x + threadIdx.x;
    if (i >= n4) return;
    float4 v = ((const float4*)in)[i];
    __half2* op = (__half2*)o;
    op[2 * i]     = __floats2half2_rn(v.x, v.y);
    op[2 * i + 1] = __floats2half2_rn(v.z, v.w);
}

// W1 * gamma[d] -> fp16 (row-major [HD, FD], d fast)
__global__ __launch_bounds__(256)
void cvt_w1g_kernel(const float* __restrict__ W1, const float* __restrict__ gamma,
                    __half* __restrict__ o, int n4)
{
    int i = blockIdx.x * blockDim.x + threadIdx.x;
    if (i >= n4) return;
    const int d = (i * 4) & (FD - 1);
    float4 v = ((const float4*)W1)[i];
    const float4 gg = *(const float4*)(gamma + d);
    __half2* op = (__half2*)o;
    op[2 * i]     = __floats2half2_rn(v.x * gg.x, v.y * gg.y);
    op[2 * i + 1] = __floats2half2_rn(v.z * gg.z, v.w * gg.w);
}

// r1[n] = sum_d gamma[d]*W1[n,d];  r2[n] = sum_d beta[d]*W1[n,d]. One warp per n.
__global__ __launch_bounds__(256)
void r12_kernel(const float* __restrict__ W1, const float* __restrict__ gamma,
                const float* __restrict__ beta, float* __restrict__ r1,
                float* __restrict__ r2)
{
    const int n = blockIdx.x * 8 + threadIdx.y;
    const int lane = threadIdx.x;
    const float* wr = W1 + (size_t)n * FD;
    float a = 0.0f, b = 0.0f;
    for (int d = lane * 4; d < FD; d += 128) {
        const float4 w = *(const float4*)(wr + d);
        const float4 gg = *(const float4*)(gamma + d);
        const float4 be = *(const float4*)(beta + d);
        a += w.x * gg.x + w.y * gg.y + w.z * gg.z + w.w * gg.w;
        b += w.x * be.x + w.y * be.y + w.z * be.z + w.w * be.w;
    }
    #pragma unroll
    for (int off = 16; off > 0; off >>= 1) {
        a += __shfl_down_sync(0xffffffffu, a, off);
        b += __shfl_down_sync(0xffffffffu, b, off);
    }
    if (lane == 0) { r1[n] = a; r2[n] = b; }
}

// finalize per-row LN stats from 32 deterministic partials
__global__ __launch_bounds__(256)
void rowstat_kernel(const float* __restrict__ rs, const float* __restrict__ rs2,
                    float* __restrict__ mu, float* __restrict__ inv)
{
    const int r = blockIdx.x * blockDim.x + threadIdx.x;
    if (r >= NROWS) return;
    float s1 = 0.0f, s2 = 0.0f;
    #pragma unroll
    for (int j = 0; j < NDBLK; j++) {
        s1 += rs [(size_t)j * NROWS + r];
        s2 += rs2[(size_t)j * NROWS + r];
    }
    const float m = s1 * (1.0f / FD);
    mu[r]  = m;
    inv[r] = rsqrtf(s2 * (1.0f / FD) - m * m + 1e-5f);
}

// ---------------------------------------------------------------------------
// Fused sequential scans -> raw ctx fp16 + deterministic per-row partial sums
// ---------------------------------------------------------------------------
__global__ __launch_bounds__(1024)
void scan_kernel(const float* __restrict__ x, const __half* __restrict__ omega,
                 const float* __restrict__ log_scale, __half* __restrict__ ctx,
                 float* __restrict__ rs, float* __restrict__ rs2)
{
    __shared__ float xs[32][33];
    __shared__ float os[32][33];
    __shared__ float ob[4][32][33];

    const int b  = blockIdx.y;
    const int dblk = blockIdx.x;
    const int d0 = dblk * 32;
    const int tx = threadIdx.x;
    const int ty = threadIdx.y;

    const float escale = expf(log_scale[d0 + ty]);

    const float* xp = x     + (size_t)b * S_LEN * D_DIM;
    const __half* op = omega + (size_t)b * S_LEN * D_DIM;
    __half*      cp = ctx   + (size_t)b * S_LEN * FD;
    const int rowbase = b * S_LEN;

    float c0 = 0.0f, c1 = 0.0f, c2 = 0.0f;

    for (int s0 = 0; s0 < S_LEN; s0 += 32) {
        xs[ty][tx] = xp[(size_t)(s0 + ty) * D_DIM + d0 + tx];
        os[ty][tx] = __half2float(op[(size_t)(s0 + ty) * D_DIM + d0 + tx]);
        __syncthreads();

        const float pos = (float)(s0 + tx + 1);
        float w = os[tx][ty] * escale * rsqrtf(pos);

        float pl = w;
        #pragma unroll
        for (int off = 1; off < 32; off <<= 1) {
            float t = __shfl_up_sync(0xffffffffu, pl, off);
            if (tx >= off) pl += t;
        }
        const float phi = c0 + pl;
        c0 += __shfl_sync(0xffffffffu, pl, 31);

        float sv, cv;
        sincosf(phi, &sv, &cv);
        const float xv  = xs[tx][ty];
        const float cmr = xv * cv;
        const float cmi = xv * sv;

        float pr = cmr;
        #pragma unroll
        for (int off = 1; off < 32; off <<= 1) {
            float t = __shfl_up_sync(0xffffffffu, pr, off);
            if (tx >= off) pr += t;
        }
        float pi = cmi;
        #pragma unroll
        for (int off = 1; off < 32; off <<= 1) {
            float t = __shfl_up_sync(0xffffffffu, pi, off);
            if (tx >= off) pi += t;
        }

        const float memr = (c1 + pr) / pos;
        const float memi = (c2 + pi) / pos;
        c1 += __shfl_sync(0xffffffffu, pr, 31);
        c2 += __shfl_sync(0xffffffffu, pi, 31);

        const float retr = memr * cv + memi * sv;
        const float reti = memi * cv - memr * sv;

        ob[0][tx][ty] = cmr;
        ob[1][tx][ty] = cmi;
        ob[2][tx][ty] = retr;
        ob[3][tx][ty] = reti;
        __syncthreads();

        // store phase: thread (tx=d-local=lane, ty=s-local=warp)
        const float v0 = ob[0][ty][tx];
        const float v1 = ob[1][ty][tx];
        const float v2 = ob[2][ty][tx];
        const float v3 = ob[3][ty][tx];
        const size_t ro = (size_t)(s0 + ty) * FD + d0 + tx;
        cp[ro]             = __float2half(v0);
        cp[ro + D_DIM]     = __float2half(v1);
        cp[ro + 2 * D_DIM] = __float2half(v2);
        cp[ro + 3 * D_DIM] = __float2half(v3);

        // deterministic per-row partial sums over this block's 32 channels
        float ls  = v0 + v1 + v2 + v3;
        float ls2 = v0 * v0 + v1 * v1 + v2 * v2 + v3 * v3;
        #pragma unroll
        for (int off = 16; off > 0; off >>= 1) {
            ls  += __shfl_down_sync(0xffffffffu, ls,  off);
            ls2 += __shfl_down_sync(0xffffffffu, ls2, off);
        }
        if (tx == 0) {
            const size_t pidx = (size_t)dblk * NROWS + rowbase + s0 + ty;
            rs [pidx] = ls;
            rs2[pidx] = ls2;
        }
        __syncthreads();
    }
}

// ---------------------------------------------------------------------------
extern "C" void kernel_launch(void* const* d_in, const int* in_sizes, int n_in,
                              void* d_out, int out_size)
{
    const float* x         = (const float*)d_in[0];
    const float* W_omega   = (const float*)d_in[1];
    const float* b_omega   = (const float*)d_in[2];
    const float* log_scale = (const float*)d_in[3];
    const float* ln_gamma  = (const float*)d_in[4];
    const float* ln_beta   = (const float*)d_in[5];
    const float* W1        = (const float*)d_in[6];
    const float* b1        = (const float*)d_in[7];
    const float* W2        = (const float*)d_in[8];
    const float* b2        = (const float*)d_in[9];
    float* out = (float*)d_out;

    __half *xf, *w0f, *omega_p, *cf, *w1g, *w2f, *h1f;
    float *rs, *rs2, *mu, *inv, *r1, *r2;
    cudaGetSymbolAddress((void**)&xf,      g_xf);
    cudaGetSymbolAddress((void**)&w0f,     g_w0f);
    cudaGetSymbolAddress((void**)&omega_p, g_omega);
    cudaGetSymbolAddress((void**)&cf,      g_cf);
    cudaGetSymbolAddress((void**)&w1g,     g_w1g);
    cudaGetSymbolAddress((void**)&w2f,     g_w2f);
    cudaGetSymbolAddress((void**)&h1f,     g_h1f);
    cudaGetSymbolAddress((void**)&rs,      g_rs);
    cudaGetSymbolAddress((void**)&rs2,     g_rs2);
    cudaGetSymbolAddress((void**)&mu,      g_mu);
    cudaGetSymbolAddress((void**)&inv,     g_inv);
    cudaGetSymbolAddress((void**)&r1,      g_r1);
    cudaGetSymbolAddress((void**)&r2,      g_r2);

    cudaFuncSetAttribute(gemm_f16_kernel<0>, cudaFuncAttributeMaxDynamicSharedMemorySize, GEMM_DSMF);
    cudaFuncSetAttribute(gemm_f16_kernel<1>, cudaFuncAttributeMaxDynamicSharedMemorySize, GEMM_DSMF);
    cudaFuncSetAttribute(gemm_f16_kernel<2>, cudaFuncAttributeMaxDynamicSharedMemorySize, GEMM_DSMF);

    // operand prep
    {
        int n4 = NROWS * D_DIM / 4;
        cvt_f16_kernel<<<(n4 + 255) / 256, 256>>>(x, xf, n4);
        n4 = D_DIM * D_DIM / 4;
        cvt_f16_kernel<<<(n4 + 255) / 256, 256>>>(W_omega, w0f, n4);
        n4 = HD * FD / 4;
        cvt_w1g_kernel<<<(n4 + 255) / 256, 256>>>(W1, ln_gamma, w1g, n4);
        n4 = D_DIM * HD / 4;
        cvt_f16_kernel<<<(n4 + 255) / 256, 256>>>(W2, w2f, n4);
        r12_kernel<<<HD / 8, dim3(32, 8)>>>(W1, ln_gamma, ln_beta, r1, r2);
    }

    // 1) omega = x @ W_omega^T + b_omega  (1-term fp16, f16 out)
    gemm_f16_kernel<0><<<dim3(D_DIM / 128, NROWS / 128), 256, GEMM_DSMF>>>(
        xf, w0f, b_omega, nullptr, nullptr, nullptr, nullptr, nullptr,
        nullptr, omega_p, NROWS, D_DIM, D_DIM);

    // 2) scans -> raw ctx f16 + LN partial sums
    scan_kernel<<<dim3(NDBLK, B_DIM), dim3(32, 32)>>>(x, omega_p, log_scale, cf, rs, rs2);

    // 3) finalize per-row mu, inv
    rowstat_kernel<<<(NROWS + 255) / 256, 256>>>(rs, rs2, mu, inv);

    // 4) h1 = GELU(LN-affine(ctx @ (W1*gamma)^T)) -> f16   (LayerNorm fused)
    gemm_f16_kernel<1><<<dim3(HD / 128, NROWS / 128), 256, GEMM_DSMF>>>(
        cf, w1g, b1, nullptr, mu, inv, r1, r2,
        nullptr, h1f, NROWS, HD, FD);

    // 5) out = x + h1 @ W2^T + b2
    gemm_f16_kernel<2><<<dim3(D_DIM / 128, NROWS / 128), 256, GEMM_DSMF>>>(
        h1f, w2f, b2, x, nullptr, nullptr, nullptr, nullptr,
        out, nullptr, NROWS, D_DIM, HD);
}